// round 4
// baseline (speedup 1.0000x reference)
#include <cuda_runtime.h>
#include <cstdint>

// Problem constants
constexpr int BATCH = 32;
constexpr int NT    = 320;   // template tokens
constexpr int LX    = 704;
constexpr int CH    = 768;
constexpr int TMPL  = 128;
constexpr int NS    = LX - TMPL;   // 576 keys

constexpr long long Q_ELEMS  = (long long)BATCH * NT * CH;   // 7,864,320
constexpr long long KV_ELEMS = (long long)BATCH * NS * CH;   // 14,155,776
constexpr long long S_ELEMS  = (long long)BATCH * NT * NS;   // 5,898,240
constexpr long long R_ELEMS  = (long long)BATCH * NS;        // 18,432

constexpr long long OFF_Q  = 0;
constexpr long long OFF_K  = OFF_Q  + Q_ELEMS;
constexpr long long OFF_KI = OFF_K  + KV_ELEMS;
constexpr long long OFF_V  = OFF_KI + KV_ELEMS;
constexpr long long OFF_VI = OFF_V  + KV_ELEMS;
constexpr long long OFF_S  = OFF_VI + KV_ELEMS;
constexpr long long OFF_SI = OFF_S  + S_ELEMS;
constexpr long long OFF_P  = OFF_SI + S_ELEMS;
constexpr long long OFF_U  = OFF_P  + Q_ELEMS;
constexpr long long OFF_S1 = OFF_U  + Q_ELEMS;
constexpr long long OFF_S2 = OFF_S1 + R_ELEMS;
constexpr long long SCRATCH_TOTAL = OFF_S2 + R_ELEMS;  // ~92.05M floats (~368 MB)

__device__ float g_scratch[SCRATCH_TOTAL];

// ---------------------------------------------------------------------------
// Tiled fp32 GEMM: 128x128 block tile, BK=8, 256 threads, 8x8 per thread.
// TRANSB: C[m,n] = sum_k A[m,k] * B[n,k]   (B row-major N x K)
// GATHER: A row r maps to source row (r/rpb)*srpb + roff + r%rpb
// Epilogue: C = alpha*acc + beta*C_old + (D ? D : 0)
// ---------------------------------------------------------------------------
constexpr int BM = 128, BN = 128, BK = 8;

template<bool TRANSB, bool GATHER>
__global__ __launch_bounds__(256)
void sgemm(const float* __restrict__ Ag, const float* __restrict__ Bg,
           float* __restrict__ Cg, const float* __restrict__ Dg,
           int M, int N, int K, int lda, int ldb, int ldc,
           long long sA, long long sB, long long sC,
           int rpb, int srpb, int roff,
           float alpha, float beta)
{
    __shared__ __align__(16) float As[BK][BM];
    __shared__ __align__(16) float Bs[BK][BN];

    const int tid = threadIdx.x;
    const int bz  = blockIdx.z;
    const float* A = Ag + bz * sA;
    const float* B = Bg + bz * sB;
    float*       C = Cg + bz * sC;
    const float* D = Dg;  // only used non-batched

    const int rowBase = blockIdx.y * BM;
    const int colBase = blockIdx.x * BN;

    // A tile load mapping: each thread one float4 of a 128x8 tile
    const int arow = tid >> 1;            // 0..127
    const int ak   = (tid & 1) * 4;       // 0 or 4
    const int gr   = rowBase + arow;
    const bool avalid = (gr < M);
    long long aoff = 0;
    if (avalid) {
        int src = gr;
        if (GATHER) src = (gr / rpb) * srpb + roff + (gr % rpb);
        aoff = (long long)src * lda + ak;
    }

    // B tile load mapping
    int brow, bcol; bool bvalid; long long boff = 0;
    if (!TRANSB) {
        brow = tid >> 5;                  // k-row 0..7
        bcol = (tid & 31) * 4;            // 0..124
        bvalid = (colBase + bcol) < N;
        if (bvalid) boff = (long long)brow * ldb + colBase + bcol;
    } else {
        brow = tid >> 1;                  // n index 0..127
        bcol = (tid & 1) * 4;             // k offset 0 or 4
        bvalid = (colBase + brow) < N;
        if (bvalid) boff = (long long)(colBase + brow) * ldb + bcol;
    }

    const int tx = tid & 15, ty = tid >> 4;

    float acc[8][8];
#pragma unroll
    for (int i = 0; i < 8; i++)
#pragma unroll
        for (int j = 0; j < 8; j++) acc[i][j] = 0.f;

    for (int k0 = 0; k0 < K; k0 += BK) {
        float4 a4 = make_float4(0.f, 0.f, 0.f, 0.f);
        if (avalid) a4 = *reinterpret_cast<const float4*>(A + aoff + k0);
        float4 b4 = make_float4(0.f, 0.f, 0.f, 0.f);
        if (!TRANSB) {
            if (bvalid) b4 = *reinterpret_cast<const float4*>(B + boff + (long long)k0 * ldb);
        } else {
            if (bvalid) b4 = *reinterpret_cast<const float4*>(B + boff + k0);
        }
        __syncthreads();   // previous tile's compute done
        As[ak + 0][arow] = a4.x; As[ak + 1][arow] = a4.y;
        As[ak + 2][arow] = a4.z; As[ak + 3][arow] = a4.w;
        if (!TRANSB) {
            *reinterpret_cast<float4*>(&Bs[brow][bcol]) = b4;
        } else {
            Bs[bcol + 0][brow] = b4.x; Bs[bcol + 1][brow] = b4.y;
            Bs[bcol + 2][brow] = b4.z; Bs[bcol + 3][brow] = b4.w;
        }
        __syncthreads();

#pragma unroll
        for (int kk = 0; kk < BK; kk++) {
            float4 a0 = *reinterpret_cast<const float4*>(&As[kk][ty * 4]);
            float4 a1 = *reinterpret_cast<const float4*>(&As[kk][64 + ty * 4]);
            float4 b0 = *reinterpret_cast<const float4*>(&Bs[kk][tx * 4]);
            float4 b1 = *reinterpret_cast<const float4*>(&Bs[kk][64 + tx * 4]);
            float a[8] = {a0.x, a0.y, a0.z, a0.w, a1.x, a1.y, a1.z, a1.w};
            float b[8] = {b0.x, b0.y, b0.z, b0.w, b1.x, b1.y, b1.z, b1.w};
#pragma unroll
            for (int i = 0; i < 8; i++)
#pragma unroll
                for (int j = 0; j < 8; j++)
                    acc[i][j] = fmaf(a[i], b[j], acc[i][j]);
        }
    }

    // Epilogue
#pragma unroll
    for (int ih = 0; ih < 2; ih++) {
#pragma unroll
        for (int ii = 0; ii < 4; ii++) {
            int r = rowBase + ih * 64 + ty * 4 + ii;
            if (r >= M) continue;
            int i = ih * 4 + ii;
#pragma unroll
            for (int jh = 0; jh < 2; jh++) {
                int c = colBase + jh * 64 + tx * 4;
                if (c >= N) continue;
                long long off = (long long)r * ldc + c;
                float4 res;
                res.x = alpha * acc[i][jh * 4 + 0];
                res.y = alpha * acc[i][jh * 4 + 1];
                res.z = alpha * acc[i][jh * 4 + 2];
                res.w = alpha * acc[i][jh * 4 + 3];
                if (beta != 0.f) {
                    float4 o = *reinterpret_cast<const float4*>(C + off);
                    res.x += beta * o.x; res.y += beta * o.y;
                    res.z += beta * o.z; res.w += beta * o.w;
                }
                if (D) {
                    float4 d4 = *reinterpret_cast<const float4*>(D + off);
                    res.x += d4.x; res.y += d4.y; res.z += d4.z; res.w += d4.w;
                }
                *reinterpret_cast<float4*>(C + off) = res;
            }
        }
    }
}

// ---------------------------------------------------------------------------
// Block reductions (256 threads)
// ---------------------------------------------------------------------------
__device__ __forceinline__ float block_reduce_max(float v) {
    __shared__ float red[8];
    int lane = threadIdx.x & 31, wid = threadIdx.x >> 5;
#pragma unroll
    for (int o = 16; o; o >>= 1) v = fmaxf(v, __shfl_xor_sync(0xffffffffu, v, o));
    if (lane == 0) red[wid] = v;
    __syncthreads();
    if (wid == 0) {
        v = (lane < 8) ? red[lane] : -3.4e38f;
#pragma unroll
        for (int o = 4; o; o >>= 1) v = fmaxf(v, __shfl_xor_sync(0xffffffffu, v, o));
        if (lane == 0) red[0] = v;
    }
    __syncthreads();
    v = red[0];
    __syncthreads();
    return v;
}

__device__ __forceinline__ float block_reduce_sum(float v) {
    __shared__ float red[8];
    int lane = threadIdx.x & 31, wid = threadIdx.x >> 5;
#pragma unroll
    for (int o = 16; o; o >>= 1) v += __shfl_xor_sync(0xffffffffu, v, o);
    if (lane == 0) red[wid] = v;
    __syncthreads();
    if (wid == 0) {
        v = (lane < 8) ? red[lane] : 0.f;
#pragma unroll
        for (int o = 4; o; o >>= 1) v += __shfl_xor_sync(0xffffffffu, v, o);
        if (lane == 0) red[0] = v;
    }
    __syncthreads();
    v = red[0];
    __syncthreads();
    return v;
}

// ---------------------------------------------------------------------------
// Row softmax over 576 columns, in place. grid = B*NT rows, block = 256
// ---------------------------------------------------------------------------
__global__ __launch_bounds__(256) void softmax_kernel(float* __restrict__ S) {
    const int cols = NS;
    long long base = (long long)blockIdx.x * cols;
    __shared__ float buf[NS];
    int tid = threadIdx.x;
    float m = -3.4e38f;
    for (int c = tid; c < cols; c += 256) {
        float v = S[base + c]; buf[c] = v; m = fmaxf(m, v);
    }
    m = block_reduce_max(m);
    float s = 0.f;
    for (int c = tid; c < cols; c += 256) {
        float e = expf(buf[c] - m); buf[c] = e; s += e;
    }
    s = block_reduce_sum(s);
    float inv = 1.f / s;
    for (int c = tid; c < cols; c += 256) S[base + c] = buf[c] * inv;
}

// ---------------------------------------------------------------------------
// Per-(b,n) sign counts over t: s1 = rgb+eq, s2 = 1-rgb (= tir+eq)
// ---------------------------------------------------------------------------
__global__ __launch_bounds__(256) void ratio_kernel(const float* __restrict__ S,
                                                    const float* __restrict__ Si,
                                                    float* __restrict__ s1,
                                                    float* __restrict__ s2) {
    int idx = blockIdx.x * blockDim.x + threadIdx.x;
    if (idx >= BATCH * NS) return;
    int b = idx / NS, n = idx - b * NS;
    const float* a  = S  + (long long)b * NT * NS + n;
    const float* ai = Si + (long long)b * NT * NS + n;
    int pos = 0, eq = 0;
    for (int t = 0; t < NT; t++) {
        float x = a[(long long)t * NS];
        float y = ai[(long long)t * NS];
        pos += (x > y);
        eq  += (x == y);
    }
    float rgb = pos * (1.f / NT);
    float eqr = eq  * (1.f / NT);
    s1[idx] = rgb + eqr;
    s2[idx] = 1.f - rgb;
}

// ---------------------------------------------------------------------------
// x_s = v * s1[row] + vi * s2[row]  -> out[0 : B*NS*CH]
// ---------------------------------------------------------------------------
__global__ __launch_bounds__(256) void xs_kernel(const float* __restrict__ V,
                                                 const float* __restrict__ VI,
                                                 const float* __restrict__ s1,
                                                 const float* __restrict__ s2,
                                                 float* __restrict__ out) {
    long long i = (long long)blockIdx.x * blockDim.x + threadIdx.x;
    const long long total4 = KV_ELEMS / 4;
    if (i >= total4) return;
    int row = (int)((i * 4) / CH);
    float a = s1[row], b = s2[row];
    float4 v4 = reinterpret_cast<const float4*>(V)[i];
    float4 w4 = reinterpret_cast<const float4*>(VI)[i];
    float4 r;
    r.x = v4.x * a + w4.x * b;
    r.y = v4.y * a + w4.y * b;
    r.z = v4.z * a + w4.z * b;
    r.w = v4.w * a + w4.w * b;
    reinterpret_cast<float4*>(out)[i] = r;
}

// ---------------------------------------------------------------------------
// LayerNorm over last dim (768). grid = B*NT rows, block = 256
// ---------------------------------------------------------------------------
__global__ __launch_bounds__(256) void ln_kernel(const float* __restrict__ U,
                                                 const float* __restrict__ gamma,
                                                 const float* __restrict__ beta,
                                                 float* __restrict__ out) {
    long long base = (long long)blockIdx.x * CH;
    __shared__ float buf[CH];
    int tid = threadIdx.x;
    float s = 0.f;
    for (int c = tid; c < CH; c += 256) {
        float v = U[base + c]; buf[c] = v; s += v;
    }
    s = block_reduce_sum(s);
    float mu = s * (1.f / CH);
    float vs = 0.f;
    for (int c = tid; c < CH; c += 256) {
        float d = buf[c] - mu; vs += d * d;
    }
    vs = block_reduce_sum(vs);
    float inv = rsqrtf(vs * (1.f / CH) + 1e-5f);
    for (int c = tid; c < CH; c += 256)
        out[base + c] = (buf[c] - mu) * inv * gamma[c] + beta[c];
}

// ---------------------------------------------------------------------------
// Launcher
// ---------------------------------------------------------------------------
extern "C" void kernel_launch(void* const* d_in, const int* in_sizes, int n_in,
                              void* d_out, int out_size) {
    const float* T     = (const float*)d_in[0];
    const float* x     = (const float*)d_in[1];
    const float* xi    = (const float*)d_in[2];
    const float* Wq    = (const float*)d_in[3];
    const float* Wk    = (const float*)d_in[4];
    const float* Wv    = (const float*)d_in[5];
    const float* Wout  = (const float*)d_in[6];
    const float* gamma = (const float*)d_in[7];
    const float* beta  = (const float*)d_in[8];
    float* out = (float*)d_out;

    void* sp = nullptr;
    cudaGetSymbolAddress(&sp, g_scratch);
    float* s = (float*)sp;
    float* Q  = s + OFF_Q;
    float* K  = s + OFF_K;
    float* KI = s + OFF_KI;
    float* V  = s + OFF_V;
    float* VI = s + OFF_VI;
    float* S  = s + OFF_S;
    float* SI = s + OFF_SI;
    float* P  = s + OFF_P;
    float* U  = s + OFF_U;
    float* S1 = s + OFF_S1;
    float* S2 = s + OFF_S2;

    const float scale = 1.0f / sqrtf((float)CH);
    const int MQ = BATCH * NT;   // 10240
    const int MK = BATCH * NS;   // 18432

    auto grid = [](int M, int N, int Z) {
        return dim3((unsigned)((N + BN - 1) / BN), (unsigned)((M + BM - 1) / BM), (unsigned)Z);
    };

    // 1) q = T @ Wq
    sgemm<false, false><<<grid(MQ, CH, 1), 256>>>(
        T, Wq, Q, nullptr, MQ, CH, CH, CH, CH, CH, 0, 0, 0, 0, 0, 0, 1.f, 0.f);
    // 2-5) k, ki, v, vi from gathered xs/xis rows
    sgemm<false, true><<<grid(MK, CH, 1), 256>>>(
        x, Wk, K, nullptr, MK, CH, CH, CH, CH, CH, 0, 0, 0, NS, LX, TMPL, 1.f, 0.f);
    sgemm<false, true><<<grid(MK, CH, 1), 256>>>(
        xi, Wk, KI, nullptr, MK, CH, CH, CH, CH, CH, 0, 0, 0, NS, LX, TMPL, 1.f, 0.f);
    sgemm<false, true><<<grid(MK, CH, 1), 256>>>(
        x, Wv, V, nullptr, MK, CH, CH, CH, CH, CH, 0, 0, 0, NS, LX, TMPL, 1.f, 0.f);
    sgemm<false, true><<<grid(MK, CH, 1), 256>>>(
        xi, Wv, VI, nullptr, MK, CH, CH, CH, CH, CH, 0, 0, 0, NS, LX, TMPL, 1.f, 0.f);

    // 6-7) S = scale * q @ k^T (batched), Si likewise
    sgemm<true, false><<<grid(NT, NS, BATCH), 256>>>(
        Q, K, S, nullptr, NT, NS, CH, CH, CH, NS,
        (long long)NT * CH, (long long)NS * CH, (long long)NT * NS,
        0, 0, 0, scale, 0.f);
    sgemm<true, false><<<grid(NT, NS, BATCH), 256>>>(
        Q, KI, SI, nullptr, NT, NS, CH, CH, CH, NS,
        (long long)NT * CH, (long long)NS * CH, (long long)NT * NS,
        0, 0, 0, scale, 0.f);

    // 8-9) row softmax in place
    softmax_kernel<<<MQ, 256>>>(S);
    softmax_kernel<<<MQ, 256>>>(SI);

    // 10) sign-count ratios
    ratio_kernel<<<(BATCH * NS + 255) / 256, 256>>>(S, SI, S1, S2);

    // 11) x_s -> out[0 : KV_ELEMS]
    xs_kernel<<<(unsigned)(KV_ELEMS / 4 / 256), 256>>>(V, VI, S1, S2, out);

    // 12-13) P = aw @ v + awi @ vi (batched, second accumulates)
    sgemm<false, false><<<grid(NT, CH, BATCH), 256>>>(
        S, V, P, nullptr, NT, CH, NS, NS, CH, CH,
        (long long)NT * NS, (long long)NS * CH, (long long)NT * CH,
        0, 0, 0, 1.f, 0.f);
    sgemm<false, false><<<grid(NT, CH, BATCH), 256>>>(
        SI, VI, P, nullptr, NT, CH, NS, NS, CH, CH,
        (long long)NT * NS, (long long)NS * CH, (long long)NT * CH,
        0, 0, 0, 1.f, 1.f);

    // 14) U = P @ Wout + T  (single shared-Wout GEMM with additive epilogue)
    sgemm<false, false><<<grid(MQ, CH, 1), 256>>>(
        P, Wout, U, T, MQ, CH, CH, CH, CH, CH, 0, 0, 0, 0, 0, 0, 1.f, 0.f);

    // 15) T_new = LayerNorm(U) -> out[KV_ELEMS : ]
    ln_kernel<<<MQ, 256>>>(U, gamma, beta, out + KV_ELEMS);
}